// round 2
// baseline (speedup 1.0000x reference)
#include <cuda_runtime.h>

// SSIM loss, fully fused: 5 depthwise separable 11x11 Gaussian convs
// (p, t, p^2, t^2, p*t) + SSIM map + global mean, in one pass over HBM.
//
// Tile: 32x32 outputs per block, halo 5 each side (42x42 staged in smem).
// Horizontal pass stages 5 conv-h fields in smem; vertical pass + SSIM +
// reduction in registers. Gaussian weights are compile-time constants so
// ptxas emits FFMA-imm (rt=1/SMSP on sm_103a, 2x the 3-reg FFMA rate).

#define TW    32
#define TH    32
#define HALO  5
#define EW    (TW + 2*HALO)   // 42
#define EH    (TH + 2*HALO)   // 42
#define SPITCH 44             // pitch for input tiles
#define HPITCH 33             // pitch for h-pass arrays

#define IMG_H 512
#define IMG_W 512
#define N_PLANES 96           // 32 * 3
#define N_PIX 25165824.0      // 32*3*512*512

// Gaussian(σ=1.5, size 11), normalized.
__device__ constexpr float GW[11] = {
    0.00102838f, 0.00759877f, 0.03600077f, 0.10936071f, 0.21300553f,
    0.26601175f,
    0.21300553f, 0.10936071f, 0.03600077f, 0.00759877f, 0.00102838f
};

__device__ double g_acc;

__global__ void ssim_init_kernel() { g_acc = 0.0; }

__global__ __launch_bounds__(256)
void ssim_tile_kernel(const float* __restrict__ pred,
                      const float* __restrict__ targ)
{
    __shared__ float sp [EH][SPITCH];
    __shared__ float st [EH][SPITCH];
    __shared__ float h1 [EH][HPITCH];   // conv_h(p)
    __shared__ float h2 [EH][HPITCH];   // conv_h(t)
    __shared__ float hpp[EH][HPITCH];   // conv_h(p*p)
    __shared__ float htt[EH][HPITCH];   // conv_h(t*t)
    __shared__ float hpt[EH][HPITCH];   // conv_h(p*t)
    __shared__ float red[8];

    const int tid = threadIdx.x;
    const int ty0 = blockIdx.y * TH;
    const int tx0 = blockIdx.x * TW;
    const size_t pbase = (size_t)blockIdx.z * (IMG_H * IMG_W);

    // ---- load halo tiles (zero padding at image borders) ----
    for (int idx = tid; idx < EH * EW; idx += 256) {
        int r = idx / EW;
        int c = idx - r * EW;
        int gy = ty0 + r - HALO;
        int gx = tx0 + c - HALO;
        bool ok = ((unsigned)gy < (unsigned)IMG_H) & ((unsigned)gx < (unsigned)IMG_W);
        float a = 0.f, b = 0.f;
        if (ok) {
            size_t off = pbase + (size_t)gy * IMG_W + gx;
            a = pred[off];
            b = targ[off];
        }
        sp[r][c] = a;
        st[r][c] = b;
    }
    __syncthreads();

    // ---- horizontal pass: each work item = 4 adjacent outputs in x ----
    // 42 rows * 8 col-groups = 336 items over 256 threads
    for (int g = tid; g < EH * (TW / 4); g += 256) {
        int r  = g >> 3;
        int c0 = (g & 7) * 4;
        float acc[5][4];
        #pragma unroll
        for (int f = 0; f < 5; f++)
            #pragma unroll
            for (int j = 0; j < 4; j++) acc[f][j] = 0.f;

        #pragma unroll
        for (int i = 0; i < 14; i++) {
            float a = sp[r][c0 + i];
            float b = st[r][c0 + i];
            float aa = a * a;
            float bb = b * b;
            float ab = a * b;
            #pragma unroll
            for (int j = 0; j < 4; j++) {
                int k = i - j;
                if (k >= 0 && k <= 10) {
                    acc[0][j] += GW[k] * a;
                    acc[1][j] += GW[k] * b;
                    acc[2][j] += GW[k] * aa;
                    acc[3][j] += GW[k] * bb;
                    acc[4][j] += GW[k] * ab;
                }
            }
        }
        #pragma unroll
        for (int j = 0; j < 4; j++) {
            h1 [r][c0 + j] = acc[0][j];
            h2 [r][c0 + j] = acc[1][j];
            hpp[r][c0 + j] = acc[2][j];
            htt[r][c0 + j] = acc[3][j];
            hpt[r][c0 + j] = acc[4][j];
        }
    }
    __syncthreads();

    // ---- vertical pass + SSIM: thread -> (x, 4 adjacent y) ----
    const int x  = tid & 31;
    const int y0 = (tid >> 5) * 4;

    float acc[5][4];
    #pragma unroll
    for (int f = 0; f < 5; f++)
        #pragma unroll
        for (int j = 0; j < 4; j++) acc[f][j] = 0.f;

    #pragma unroll
    for (int i = 0; i < 14; i++) {
        int row = y0 + i;
        float v1 = h1 [row][x];
        float v2 = h2 [row][x];
        float vp = hpp[row][x];
        float vt = htt[row][x];
        float vx = hpt[row][x];
        #pragma unroll
        for (int j = 0; j < 4; j++) {
            int k = i - j;
            if (k >= 0 && k <= 10) {
                acc[0][j] += GW[k] * v1;
                acc[1][j] += GW[k] * v2;
                acc[2][j] += GW[k] * vp;
                acc[3][j] += GW[k] * vt;
                acc[4][j] += GW[k] * vx;
            }
        }
    }

    float lsum = 0.f;
    const float C1 = 1e-4f;   // 0.01^2
    const float C2 = 9e-4f;   // 0.03^2
    #pragma unroll
    for (int j = 0; j < 4; j++) {
        float mu1  = acc[0][j];
        float mu2  = acc[1][j];
        float m1s  = mu1 * mu1;
        float m2s  = mu2 * mu2;
        float m12  = mu1 * mu2;
        float s1   = acc[2][j] - m1s;
        float s2   = acc[3][j] - m2s;
        float s12  = acc[4][j] - m12;
        float num  = (2.f * m12 + C1) * (2.f * s12 + C2);
        float den  = (m1s + m2s + C1) * (s1 + s2 + C2) + 1e-8f;
        lsum += num / den;
    }

    // ---- block reduce + global accumulate ----
    #pragma unroll
    for (int o = 16; o; o >>= 1)
        lsum += __shfl_xor_sync(0xffffffffu, lsum, o);
    if ((tid & 31) == 0) red[tid >> 5] = lsum;
    __syncthreads();
    if (tid == 0) {
        float s = 0.f;
        #pragma unroll
        for (int w = 0; w < 8; w++) s += red[w];
        atomicAdd(&g_acc, (double)s);
    }
}

__global__ void ssim_fin_kernel(float* __restrict__ out) {
    out[0] = (float)(1.0 - g_acc * (1.0 / N_PIX));
}

extern "C" void kernel_launch(void* const* d_in, const int* in_sizes, int n_in,
                              void* d_out, int out_size)
{
    const float* pred = (const float*)d_in[0];
    const float* targ = (const float*)d_in[1];

    ssim_init_kernel<<<1, 1>>>();
    dim3 grid(IMG_W / TW, IMG_H / TH, N_PLANES);   // 16 x 16 x 96
    ssim_tile_kernel<<<grid, 256>>>(pred, targ);
    ssim_fin_kernel<<<1, 1>>>((float*)d_out);
}